// round 4
// baseline (speedup 1.0000x reference)
#include <cuda_runtime.h>

// ScoreMechain fused kernel — fp32, warp-per-TWO-samples, weights in shared.
// S=2: every per-lane weight load from shared is amortized over two samples,
// halving the dominant smem-crossbar traffic (ncu R3: L1=81.7% binding).

#define FULL 0xffffffffu

constexpr int J  = 17;
constexpr int NQ = 8;
constexpr int NWARP = 8;
constexpr int NT = NWARP * 32;

// shared-memory float offsets (weights identical to R3 layout)
constexpr int OFF_WUP4 = 0;            // [8][544][4] packed quads over input dim
constexpr int OFF_WUPT = 17408;        // [544][2]   tail inputs i=32,33
constexpr int OFF_BUP  = 18496;        // [544]
constexpr int OFF_PB   = 19040;        // [544] pbias
constexpr int OFF_WUD  = 19584;        // [32][32]
constexpr int OFF_WQ   = 20608;
constexpr int OFF_WK   = 21632;
constexpr int OFF_WV   = 22656;
constexpr int OFF_WD1  = 23680;
constexpr int OFF_WD2  = 24704;
constexpr int OFF_BQ   = 25728;
constexpr int OFF_BK   = 25760;
constexpr int OFF_BV   = 25792;
constexpr int OFF_BD1  = 25824;
constexpr int OFF_BD2  = 25856;
constexpr int OFF_WS   = 25888;
constexpr int OFF_BS   = 25920;        // 1 float (+3 pad)
constexpr int OFF_WARP = 25924;        // per-warp scratch base
// per-warp S=2 layout (floats):
//   bufU0[544] bufU1[544] bufA0[544] bufA1[544]
//   kpad0[564] kpad1[564] misc0[256] misc1[256]
constexpr int WSTRIDE  = 3816;
constexpr int SMEM_FLOATS = OFF_WARP + NWARP * WSTRIDE;   // 56452 -> 225808 B

__device__ int g_mask_mode;   // 0 = uint8 per element, 1 = 32-bit word per element

__device__ __forceinline__ float leaky(float v) { return v > 0.f ? v : 0.01f * v; }

// Detect mask dtype: reference guarantees exactly 9 nonzero entries per 17-row.
__global__ void detect_mask_kernel(const void* __restrict__ mraw)
{
    const unsigned char* m8 = (const unsigned char*)mraw;
    int lane = threadIdx.x;
    int bad8 = 0;
    #pragma unroll
    for (int s = 0; s < 2; s++) {
        int b = lane * 2 + s;
        int cnt = 0;
        for (int j = 0; j < J; j++) cnt += (m8[b * J + j] != 0);
        bad8 |= (cnt != 9);
    }
    unsigned any_bad = __ballot_sync(FULL, bad8);
    if (lane == 0) g_mask_mode = (any_bad == 0u) ? 0 : 1;
}

__global__ void __launch_bounds__(NT, 1)
score_mechain_kernel(const float* __restrict__ x,
                     const void* __restrict__ mraw,
                     const float* __restrict__ positions,
                     const float* __restrict__ W_up, const float* __restrict__ b_up,
                     const float* __restrict__ W_ud, const float* __restrict__ b_ud,
                     const float* __restrict__ W_q,  const float* __restrict__ b_q,
                     const float* __restrict__ W_k,  const float* __restrict__ b_k,
                     const float* __restrict__ W_v,  const float* __restrict__ b_v,
                     const float* __restrict__ W_d1, const float* __restrict__ b_d1,
                     const float* __restrict__ W_d2, const float* __restrict__ b_d2,
                     const float* __restrict__ W_s,  const float* __restrict__ b_s,
                     float* __restrict__ out, int B)
{
    extern __shared__ float smem[];
    const int tid = threadIdx.x;

    // ---------------- weight staging (once per CTA) ----------------
    for (int i = tid; i < 8 * 544 * 4; i += NT) {
        int iq = i / 2176, r = i % 2176, c = r >> 2, t = r & 3;
        smem[OFF_WUP4 + i] = W_up[(iq * 4 + t) * 544 + c];
    }
    for (int i = tid; i < 544 * 2; i += NT) {
        int c = i >> 1, t = i & 1;
        smem[OFF_WUPT + i] = W_up[(32 + t) * 544 + c];
    }
    for (int i = tid; i < 544; i += NT) smem[OFF_BUP + i] = b_up[i];
    for (int i = tid; i < 1024; i += NT) {
        smem[OFF_WUD + i] = W_ud[i];        // rows 0..31 of (64,32) row-major
        smem[OFF_WQ  + i] = W_q[i];
        smem[OFF_WK  + i] = W_k[i];
        smem[OFF_WV  + i] = W_v[i];
        smem[OFF_WD1 + i] = W_d1[i];
        smem[OFF_WD2 + i] = W_d2[i];
    }
    for (int i = tid; i < 32; i += NT) {
        smem[OFF_BQ  + i] = b_q[i];
        smem[OFF_BK  + i] = b_k[i];
        smem[OFF_BV  + i] = b_v[i];
        smem[OFF_BD1 + i] = b_d1[i];
        smem[OFF_BD2 + i] = b_d2[i];
        smem[OFF_WS  + i] = W_s[i];
    }
    if (tid == 0) smem[OFF_BS] = b_s[0];
    // pbias[j][o] = b_ud[o] + sum_h2 positions[j][h2] * W_ud[32+h2][o]
    for (int i = tid; i < 544; i += NT) {
        int j = i >> 5, o = i & 31;
        float acc = b_ud[o];
        #pragma unroll 8
        for (int h2 = 0; h2 < 32; h2++)
            acc += positions[j * 32 + h2] * W_ud[(32 + h2) * 32 + o];
        smem[OFF_PB + i] = acc;
    }
    __syncthreads();

    const int warpId = tid >> 5, lane = tid & 31;
    float* ws    = smem + OFF_WARP + warpId * WSTRIDE;
    float* bufU0 = ws;
    float* bufU1 = ws + 544;
    float* bufA0 = ws + 1088;
    float* bufA1 = ws + 1632;
    float* kpad0 = ws + 2176;   // k padded (17x33), later o-scratch (8x32)
    float* kpad1 = ws + 2740;
    float* misc0 = ws + 3304;   // x(34) -> q(8x32) -> p(8x20) -> d1-out(8x32)
    float* misc1 = ws + 3560;

    const int gw = blockIdx.x * NWARP + warpId;
    const int nw = gridDim.x * NWARP;
    const float iscale = 0.17677669529663687f;  // 1/sqrt(32)

    const int mask_mode = g_mask_mode;
    const unsigned char* mbase = (const unsigned char*)mraw;
    const int melt = (mask_mode == 0) ? 1 : 4;   // bytes per element

    for (int b0 = gw * 2; b0 < B; b0 += nw * 2) {
        const int b1 = b0 + 1;   // B even, b0 even -> always valid

        // ---- inputs ----
        misc0[lane] = x[b0 * 34 + lane];
        misc1[lane] = x[b1 * 34 + lane];
        if (lane < 2) {
            misc0[32 + lane] = x[b0 * 34 + 32 + lane];
            misc1[32 + lane] = x[b1 * 34 + 32 + lane];
        }
        unsigned mb0 = 1u, mb1 = 1u;
        if (lane < J) {
            const unsigned char* mp0 = mbase + ((size_t)b0 * J + lane) * melt;
            const unsigned char* mp1 = mbase + ((size_t)b1 * J + lane) * melt;
            unsigned v0 = mp0[0], v1 = mp1[0];
            if (melt == 4) { v0 |= mp0[1] | mp0[2] | mp0[3]; v1 |= mp1[1] | mp1[2] | mp1[3]; }
            mb0 = (v0 != 0u); mb1 = (v1 != 0u);
        }
        const unsigned occb0 = __ballot_sync(FULL, mb0 == 0u) & 0x1FFFFu;
        const unsigned occb1 = __ballot_sync(FULL, mb1 == 0u) & 0x1FFFFu;
        __syncwarp();

        // ---- up = leaky(x @ W_up + b_up) ----
        {
            float a0[J], a1[J];
            #pragma unroll
            for (int j = 0; j < J; j++) {
                float bv = smem[OFF_BUP + j * 32 + lane];
                a0[j] = bv; a1[j] = bv;
            }
            #pragma unroll
            for (int iq = 0; iq < 8; iq++) {
                float4 x0 = *reinterpret_cast<const float4*>(misc0 + 4 * iq);
                float4 x1 = *reinterpret_cast<const float4*>(misc1 + 4 * iq);
                #pragma unroll
                for (int j = 0; j < J; j++) {
                    float4 w = *reinterpret_cast<const float4*>(
                        smem + OFF_WUP4 + (iq * 544 + j * 32 + lane) * 4);
                    a0[j] += x0.x * w.x + x0.y * w.y + x0.z * w.z + x0.w * w.w;
                    a1[j] += x1.x * w.x + x1.y * w.y + x1.z * w.z + x1.w * w.w;
                }
            }
            {
                float xa0 = misc0[32], xb0 = misc0[33];
                float xa1 = misc1[32], xb1 = misc1[33];
                #pragma unroll
                for (int j = 0; j < J; j++) {
                    float2 w = *reinterpret_cast<const float2*>(
                        smem + OFF_WUPT + (j * 32 + lane) * 2);
                    a0[j] += xa0 * w.x + xb0 * w.y;
                    a1[j] += xa1 * w.x + xb1 * w.y;
                }
            }
            #pragma unroll
            for (int j = 0; j < J; j++) {
                bufU0[j * 32 + lane] = leaky(a0[j]);
                bufU1[j * 32 + lane] = leaky(a1[j]);
            }
        }
        __syncwarp();

        // ---- u = leaky(up @ Wud_top + pbias) ----
        {
            float a0[J], a1[J];
            #pragma unroll
            for (int j = 0; j < J; j++) {
                float pv = smem[OFF_PB + j * 32 + lane];
                a0[j] = pv; a1[j] = pv;
            }
            #pragma unroll
            for (int hq = 0; hq < 8; hq++) {
                float w0 = smem[OFF_WUD + (4 * hq + 0) * 32 + lane];
                float w1 = smem[OFF_WUD + (4 * hq + 1) * 32 + lane];
                float w2 = smem[OFF_WUD + (4 * hq + 2) * 32 + lane];
                float w3 = smem[OFF_WUD + (4 * hq + 3) * 32 + lane];
                #pragma unroll
                for (int j = 0; j < J; j++) {
                    float4 u0 = *reinterpret_cast<const float4*>(bufU0 + j * 32 + 4 * hq);
                    float4 u1 = *reinterpret_cast<const float4*>(bufU1 + j * 32 + 4 * hq);
                    a0[j] += u0.x * w0 + u0.y * w1 + u0.z * w2 + u0.w * w3;
                    a1[j] += u1.x * w0 + u1.y * w1 + u1.z * w2 + u1.w * w3;
                }
            }
            #pragma unroll
            for (int j = 0; j < J; j++) {
                bufA0[j * 32 + lane] = leaky(a0[j]);
                bufA1[j * 32 + lane] = leaky(a1[j]);
            }
        }
        __syncwarp();

        // ---- k (all joints) ----
        {
            float a0[J], a1[J];
            #pragma unroll
            for (int j = 0; j < J; j++) {
                float bv = smem[OFF_BK + lane];
                a0[j] = bv; a1[j] = bv;
            }
            #pragma unroll
            for (int hq = 0; hq < 8; hq++) {
                float w0 = smem[OFF_WK + (4 * hq + 0) * 32 + lane];
                float w1 = smem[OFF_WK + (4 * hq + 1) * 32 + lane];
                float w2 = smem[OFF_WK + (4 * hq + 2) * 32 + lane];
                float w3 = smem[OFF_WK + (4 * hq + 3) * 32 + lane];
                #pragma unroll
                for (int j = 0; j < J; j++) {
                    float4 u0 = *reinterpret_cast<const float4*>(bufA0 + j * 32 + 4 * hq);
                    float4 u1 = *reinterpret_cast<const float4*>(bufA1 + j * 32 + 4 * hq);
                    a0[j] += u0.x * w0 + u0.y * w1 + u0.z * w2 + u0.w * w3;
                    a1[j] += u1.x * w0 + u1.y * w1 + u1.z * w2 + u1.w * w3;
                }
            }
            #pragma unroll
            for (int j = 0; j < J; j++) {
                kpad0[j * 33 + lane] = a0[j];
                kpad1[j * 33 + lane] = a1[j];
            }
        }

        // ---- q (occluded joints only) ----
        {
            int oj0[NQ], oj1[NQ];
            unsigned t0 = occb0, t1 = occb1;
            #pragma unroll
            for (int t = 0; t < NQ; t++) {
                oj0[t] = __ffs(t0) - 1; t0 &= t0 - 1;
                oj1[t] = __ffs(t1) - 1; t1 &= t1 - 1;
            }
            float a0[NQ], a1[NQ];
            #pragma unroll
            for (int t = 0; t < NQ; t++) {
                float bv = smem[OFF_BQ + lane];
                a0[t] = bv; a1[t] = bv;
            }
            #pragma unroll
            for (int hq = 0; hq < 8; hq++) {
                float w0 = smem[OFF_WQ + (4 * hq + 0) * 32 + lane];
                float w1 = smem[OFF_WQ + (4 * hq + 1) * 32 + lane];
                float w2 = smem[OFF_WQ + (4 * hq + 2) * 32 + lane];
                float w3 = smem[OFF_WQ + (4 * hq + 3) * 32 + lane];
                #pragma unroll
                for (int t = 0; t < NQ; t++) {
                    float4 u0 = *reinterpret_cast<const float4*>(bufA0 + oj0[t] * 32 + 4 * hq);
                    float4 u1 = *reinterpret_cast<const float4*>(bufA1 + oj1[t] * 32 + 4 * hq);
                    a0[t] += u0.x * w0 + u0.y * w1 + u0.z * w2 + u0.w * w3;
                    a1[t] += u1.x * w0 + u1.y * w1 + u1.z * w2 + u1.w * w3;
                }
            }
            __syncwarp();   // x dead; misc becomes q
            #pragma unroll
            for (int t = 0; t < NQ; t++) {
                misc0[t * 32 + lane] = a0[t];
                misc1[t * 32 + lane] = a1[t];
            }
        }

        // ---- v (all joints) — overwrites bufA after all u reads done ----
        {
            float a0[J], a1[J];
            #pragma unroll
            for (int j = 0; j < J; j++) {
                float bv = smem[OFF_BV + lane];
                a0[j] = bv; a1[j] = bv;
            }
            #pragma unroll
            for (int hq = 0; hq < 8; hq++) {
                float w0 = smem[OFF_WV + (4 * hq + 0) * 32 + lane];
                float w1 = smem[OFF_WV + (4 * hq + 1) * 32 + lane];
                float w2 = smem[OFF_WV + (4 * hq + 2) * 32 + lane];
                float w3 = smem[OFF_WV + (4 * hq + 3) * 32 + lane];
                #pragma unroll
                for (int j = 0; j < J; j++) {
                    float4 u0 = *reinterpret_cast<const float4*>(bufA0 + j * 32 + 4 * hq);
                    float4 u1 = *reinterpret_cast<const float4*>(bufA1 + j * 32 + 4 * hq);
                    a0[j] += u0.x * w0 + u0.y * w1 + u0.z * w2 + u0.w * w3;
                    a1[j] += u1.x * w0 + u1.y * w1 + u1.z * w2 + u1.w * w3;
                }
            }
            __syncwarp();   // all u reads done before overwrite
            #pragma unroll
            for (int j = 0; j < J; j++) {
                bufA0[j * 32 + lane] = a0[j];
                bufA1[j * 32 + lane] = a1[j];
            }
        }
        __syncwarp();

        // ---- scores: lane = key joint ----
        {
            float s0[NQ], s1[NQ];
            #pragma unroll
            for (int t = 0; t < NQ; t++) { s0[t] = 0.f; s1[t] = 0.f; }
            #pragma unroll 8
            for (int h = 0; h < 32; h++) {
                float k0 = (lane < J) ? kpad0[lane * 33 + h] : 0.f;
                float k1 = (lane < J) ? kpad1[lane * 33 + h] : 0.f;
                #pragma unroll
                for (int t = 0; t < NQ; t++) {
                    s0[t] += misc0[t * 32 + h] * k0;
                    s1[t] += misc1[t * 32 + h] * k1;
                }
            }
            __syncwarp();   // q fully consumed; misc becomes p
            #pragma unroll
            for (int t = 0; t < NQ; t++) {
                float sa = (lane < J) ? s0[t] * iscale : -1e30f;
                float mx = sa;
                #pragma unroll
                for (int o = 16; o > 0; o >>= 1)
                    mx = fmaxf(mx, __shfl_xor_sync(FULL, mx, o));
                float e = (lane < J) ? __expf(sa - mx) : 0.f;
                float sum = e;
                #pragma unroll
                for (int o = 16; o > 0; o >>= 1)
                    sum += __shfl_xor_sync(FULL, sum, o);
                if (lane < J) misc0[t * 20 + lane] = __fdividef(e, sum);

                float sb = (lane < J) ? s1[t] * iscale : -1e30f;
                float my = sb;
                #pragma unroll
                for (int o = 16; o > 0; o >>= 1)
                    my = fmaxf(my, __shfl_xor_sync(FULL, my, o));
                float e1 = (lane < J) ? __expf(sb - my) : 0.f;
                float sum1 = e1;
                #pragma unroll
                for (int o = 16; o > 0; o >>= 1)
                    sum1 += __shfl_xor_sync(FULL, sum1, o);
                if (lane < J) misc1[t * 20 + lane] = __fdividef(e1, sum1);
            }
        }
        __syncwarp();

        // ---- o = att @ v : lane = h ----
        {
            float o0[NQ], o1[NQ];
            #pragma unroll
            for (int t = 0; t < NQ; t++) { o0[t] = 0.f; o1[t] = 0.f; }
            #pragma unroll
            for (int j = 0; j < J; j++) {
                float v0 = bufA0[j * 32 + lane];
                float v1 = bufA1[j * 32 + lane];
                #pragma unroll
                for (int t = 0; t < NQ; t++) {
                    o0[t] += misc0[t * 20 + j] * v0;
                    o1[t] += misc1[t * 20 + j] * v1;
                }
            }
            __syncwarp();   // k dead; kpad becomes o-scratch
            #pragma unroll
            for (int t = 0; t < NQ; t++) {
                kpad0[t * 32 + lane] = o0[t];
                kpad1[t * 32 + lane] = o1[t];
            }
        }
        __syncwarp();

        // ---- d1 ----
        {
            float a0[NQ], a1[NQ];
            #pragma unroll
            for (int t = 0; t < NQ; t++) {
                float bv = smem[OFF_BD1 + lane];
                a0[t] = bv; a1[t] = bv;
            }
            #pragma unroll
            for (int hq = 0; hq < 8; hq++) {
                float w0 = smem[OFF_WD1 + (4 * hq + 0) * 32 + lane];
                float w1 = smem[OFF_WD1 + (4 * hq + 1) * 32 + lane];
                float w2 = smem[OFF_WD1 + (4 * hq + 2) * 32 + lane];
                float w3 = smem[OFF_WD1 + (4 * hq + 3) * 32 + lane];
                #pragma unroll
                for (int t = 0; t < NQ; t++) {
                    float4 u0 = *reinterpret_cast<const float4*>(kpad0 + t * 32 + 4 * hq);
                    float4 u1 = *reinterpret_cast<const float4*>(kpad1 + t * 32 + 4 * hq);
                    a0[t] += u0.x * w0 + u0.y * w1 + u0.z * w2 + u0.w * w3;
                    a1[t] += u1.x * w0 + u1.y * w1 + u1.z * w2 + u1.w * w3;
                }
            }
            __syncwarp();   // p dead; misc becomes d1 output
            #pragma unroll
            for (int t = 0; t < NQ; t++) {
                misc0[t * 32 + lane] = leaky(a0[t]);
                misc1[t * 32 + lane] = leaky(a1[t]);
            }
        }
        __syncwarp();

        // ---- d2 + residual, then final reduce + sigmoid ----
        {
            int oj0[NQ], oj1[NQ];
            unsigned t0 = occb0, t1 = occb1;
            #pragma unroll
            for (int t = 0; t < NQ; t++) {
                oj0[t] = __ffs(t0) - 1; t0 &= t0 - 1;
                oj1[t] = __ffs(t1) - 1; t1 &= t1 - 1;
            }
            float a0[NQ], a1[NQ];
            #pragma unroll
            for (int t = 0; t < NQ; t++) {
                float bv = smem[OFF_BD2 + lane];
                a0[t] = bv + bufU0[oj0[t] * 32 + lane];
                a1[t] = bv + bufU1[oj1[t] * 32 + lane];
            }
            #pragma unroll
            for (int hq = 0; hq < 8; hq++) {
                float w0 = smem[OFF_WD2 + (4 * hq + 0) * 32 + lane];
                float w1 = smem[OFF_WD2 + (4 * hq + 1) * 32 + lane];
                float w2 = smem[OFF_WD2 + (4 * hq + 2) * 32 + lane];
                float w3 = smem[OFF_WD2 + (4 * hq + 3) * 32 + lane];
                #pragma unroll
                for (int t = 0; t < NQ; t++) {
                    float4 u0 = *reinterpret_cast<const float4*>(misc0 + t * 32 + 4 * hq);
                    float4 u1 = *reinterpret_cast<const float4*>(misc1 + t * 32 + 4 * hq);
                    a0[t] += u0.x * w0 + u0.y * w1 + u0.z * w2 + u0.w * w3;
                    a1[t] += u1.x * w0 + u1.y * w1 + u1.z * w2 + u1.w * w3;
                }
            }

            float wsv = smem[OFF_WS + lane];
            float out0 = 0.f, out1 = 0.f;
            #pragma unroll
            for (int t = 0; t < NQ; t++) {
                float v0 = a0[t] * wsv;
                float v1 = a1[t] * wsv;
                #pragma unroll
                for (int o = 16; o > 0; o >>= 1) {
                    v0 += __shfl_xor_sync(FULL, v0, o);
                    v1 += __shfl_xor_sync(FULL, v1, o);
                }
                if (lane == t) { out0 = v0; out1 = v1; }
            }
            if (lane < NQ) {
                float bs = smem[OFF_BS];
                out[b0 * NQ + lane] = __fdividef(1.f, 1.f + __expf(-(out0 + bs)));
                out[b1 * NQ + lane] = __fdividef(1.f, 1.f + __expf(-(out1 + bs)));
            }
        }
        __syncwarp();   // scratch reused next iteration
    }
}

extern "C" void kernel_launch(void* const* d_in, const int* in_sizes, int n_in,
                              void* d_out, int out_size)
{
    const float* x         = (const float*)d_in[0];
    const void*  mraw      = d_in[1];
    const float* positions = (const float*)d_in[2];
    const float* W_up = (const float*)d_in[3];
    const float* b_up = (const float*)d_in[4];
    const float* W_ud = (const float*)d_in[5];
    const float* b_ud = (const float*)d_in[6];
    const float* W_q  = (const float*)d_in[7];
    const float* b_q  = (const float*)d_in[8];
    const float* W_k  = (const float*)d_in[9];
    const float* b_k  = (const float*)d_in[10];
    const float* W_v  = (const float*)d_in[11];
    const float* b_v  = (const float*)d_in[12];
    const float* W_d1 = (const float*)d_in[13];
    const float* b_d1 = (const float*)d_in[14];
    const float* W_d2 = (const float*)d_in[15];
    const float* b_d2 = (const float*)d_in[16];
    const float* W_s  = (const float*)d_in[17];
    const float* b_s  = (const float*)d_in[18];
    float* out = (float*)d_out;

    const int B = in_sizes[0] / 34;
    const size_t smem_bytes = (size_t)SMEM_FLOATS * sizeof(float);

    detect_mask_kernel<<<1, 32>>>(mraw);

    cudaFuncSetAttribute(score_mechain_kernel,
                         cudaFuncAttributeMaxDynamicSharedMemorySize,
                         (int)smem_bytes);
    score_mechain_kernel<<<148, NT, smem_bytes>>>(
        x, mraw, positions, W_up, b_up, W_ud, b_ud, W_q, b_q, W_k, b_k,
        W_v, b_v, W_d1, b_d1, W_d2, b_d2, W_s, b_s, out, B);
}